// round 4
// baseline (speedup 1.0000x reference)
#include <cuda_runtime.h>
#include <cuda_bf16.h>
#include <cstdint>

// ============================================================================
// EdgeCompute: out[e] = sigmoid(relu(|x[i0[e]] - x[i1[e]]| @ W1 + b1) @ W2 + b2)
// x: [n_nodes,128] f32, indices: [2,N] int32 (JAX demotes int64!) or int64,
// W1: [128,64], b1: [64], W2: [64,1], b2: [1], out: [N] f32.
//
// Persistent kernel, warp-independent 32-edge tiles, split-bf16 (hi+lo)
// mma.sync m16n8k16, 3-term product (hi*hi + hi*lo + lo*hi) for fp32-grade
// accuracy. Index dtype auto-detected by a prepass kernel (OR of int64-high
// words == 0 <=> int64).
// ============================================================================

#define D_FEAT 128
#define HID 64
#define WPC 10
#define THREADS (WPC * 32)
#define TILE_E 32

#define A_ROW_B   272
#define A_SPLIT_B (32 * A_ROW_B)        // 8704
#define A_WARP_B  (2 * A_SPLIT_B)       // 17408
#define SM_A      0
#define SM_BHI    (WPC * A_WARP_B)                 // 174080: 2048 x uint2 hi frags
#define SM_BLO    (SM_BHI + 2048 * 8)
#define SM_PAR    (SM_BLO + 2048 * 8)              // b1[64], W2[64], b2
#define SM_BYTES  (SM_PAR + 132 * 4)               // 207,376 B < 227 KB

__device__ int g_idx_is64;   // 1 if indices are int64, 0 if int32

__device__ __forceinline__ uint32_t smem_u32(const void* p) {
    uint32_t a;
    asm("{ .reg .u64 t; cvta.to.shared.u64 t, %1; cvt.u32.u64 %0, t; }" : "=r"(a) : "l"(p));
    return a;
}
__device__ __forceinline__ uint32_t lds32(uint32_t addr) {
    uint32_t v;
    asm volatile("ld.shared.b32 %0, [%1];" : "=r"(v) : "r"(addr));
    return v;
}
__device__ __forceinline__ uint2 lds64(uint32_t addr) {
    uint2 v;
    asm volatile("ld.shared.v2.b32 {%0,%1}, [%2];" : "=r"(v.x), "=r"(v.y) : "r"(addr));
    return v;
}
__device__ __forceinline__ void sts64(uint32_t addr, uint2 v) {
    asm volatile("st.shared.v2.b32 [%0], {%1,%2};" :: "r"(addr), "r"(v.x), "r"(v.y));
}

// pack (lo16<-first arg, hi16<-second): cvt puts first PTX source in UPPER half.
__device__ __forceinline__ uint32_t pack_bf16x2(float lo, float hi) {
    uint32_t u;
    asm("cvt.rn.bf16x2.f32 %0, %1, %2;" : "=r"(u) : "f"(hi), "f"(lo));
    return u;
}

__device__ __forceinline__ void mma_bf16(float* c, const uint32_t* a, uint2 b) {
    asm volatile(
        "mma.sync.aligned.m16n8k16.row.col.f32.bf16.bf16.f32 "
        "{%0,%1,%2,%3}, {%4,%5,%6,%7}, {%8,%9}, {%0,%1,%2,%3};"
        : "+f"(c[0]), "+f"(c[1]), "+f"(c[2]), "+f"(c[3])
        : "r"(a[0]), "r"(a[1]), "r"(a[2]), "r"(a[3]), "r"(b.x), "r"(b.y));
}

// Load one m16k16 A fragment (4 u32) from the staged tile.
__device__ __forceinline__ void ld_afrag(uint32_t* f, uint32_t base, int rowbase,
                                         int g, uint32_t cb) {
    uint32_t r0 = base + (uint32_t)(rowbase + g) * A_ROW_B + cb;
    uint32_t r8 = r0 + 8 * A_ROW_B;
    f[0] = lds32(r0);        // {A[g][2t],   A[g][2t+1]}
    f[1] = lds32(r8);        // {A[g+8][2t], A[g+8][2t+1]}
    f[2] = lds32(r0 + 16);   // {A[g][2t+8], A[g][2t+9]}
    f[3] = lds32(r8 + 16);   // {A[g+8][2t+8], A[g+8][2t+9]}
}

// ---- prepass: detect index dtype. int64 nonneg small values => every high
// word is 0. For int32, "high words" are random indices: OR != 0 w.h.p. ----
__global__ void detect_idx_kernel(const int* __restrict__ idx32, int n_pairs) {
    __shared__ int s_or;
    if (threadIdx.x == 0) s_or = 0;
    __syncthreads();
    int v = 0;
    int lim = n_pairs < 4096 ? n_pairs : 4096;
    for (int j = threadIdx.x; j < lim; j += blockDim.x)
        v |= idx32[2 * j + 1];
    if (v) atomicOr(&s_or, 1);
    __syncthreads();
    if (threadIdx.x == 0) g_idx_is64 = (s_or == 0) ? 1 : 0;
}

__global__ void __launch_bounds__(THREADS, 1) edge_mlp(
    const float4* __restrict__ x4, const int* __restrict__ idx32,
    const float* __restrict__ W1, const float* __restrict__ b1,
    const float* __restrict__ W2, const float* __restrict__ b2,
    float* __restrict__ out, int n_edges, int n_nodes,
    int n_tiles, int n_warps_total)
{
    extern __shared__ char smem[];
    const uint32_t sb = smem_u32(smem);
    const int tid = threadIdx.x, wid = tid >> 5, lid = tid & 31;
    const int is64 = g_idx_is64;

    // ---- one-time: stage W1 as per-lane split-bf16 B fragments ----
    // m16n8k16 B frag, lane L (g=L/4, t=L%4), tile (ks,ns), B[k][n]=W1[k][n]:
    //   b.x = {B[16ks+2t][8ns+g], B[16ks+2t+1][...]},  b.y = k rows +8,+9
    for (int e = tid; e < 2048; e += THREADS) {
        int tile = e >> 5, lane = e & 31;
        int ks = tile >> 3, ns = tile & 7;
        int g = lane >> 2, t = lane & 3;
        int col = ns * 8 + g;
        int kb = ks * 16 + 2 * t;
        float w00 = W1[(kb    ) * HID + col];
        float w01 = W1[(kb + 1) * HID + col];
        float w10 = W1[(kb + 8) * HID + col];
        float w11 = W1[(kb + 9) * HID + col];
        uint32_t h0 = pack_bf16x2(w00, w01);
        uint32_t h1 = pack_bf16x2(w10, w11);
        uint32_t l0 = pack_bf16x2(w00 - __uint_as_float(h0 << 16),
                                  w01 - __uint_as_float(h0 & 0xffff0000u));
        uint32_t l1 = pack_bf16x2(w10 - __uint_as_float(h1 << 16),
                                  w11 - __uint_as_float(h1 & 0xffff0000u));
        sts64(sb + SM_BHI + e * 8, make_uint2(h0, h1));
        sts64(sb + SM_BLO + e * 8, make_uint2(l0, l1));
    }
    float* par = (float*)(smem + SM_PAR);
    if (tid < HID)            par[tid] = b1[tid];
    else if (tid < 2 * HID)   par[tid] = W2[tid - HID];
    if (tid == 2 * HID)       par[128] = b2[0];
    __syncthreads();

    const uint32_t aw = sb + SM_A + (uint32_t)wid * A_WARP_B;
    const int g2 = lid >> 2, t4 = lid & 3;

    // ---- persistent warp-independent tile loop ----
    for (int tile = blockIdx.x * WPC + wid; tile < n_tiles; tile += n_warps_total) {
        const int e0 = tile * TILE_E;
        const int eg = e0 + lid;
        int n0v = 0, n1v = 0;
        if (eg < n_edges) {
            if (is64) {
                n0v = idx32[2 * eg];                  // low word of int64
                n1v = idx32[2 * (n_edges + eg)];
            } else {
                n0v = idx32[eg];
                n1v = idx32[n_edges + eg];
            }
        }
        if ((unsigned)n0v >= (unsigned)n_nodes) n0v = 0;   // safety clamp
        if ((unsigned)n1v >= (unsigned)n_nodes) n1v = 0;
        __syncwarp();

        // gather + |diff| -> split-bf16 A rows (coalesced: full 512B row/edge)
        #pragma unroll 4
        for (int t = 0; t < 32; t++) {
            int r0 = __shfl_sync(0xffffffffu, n0v, t);
            int r1 = __shfl_sync(0xffffffffu, n1v, t);
            float4 a = __ldg(x4 + r0 * 32 + lid);
            float4 b = __ldg(x4 + r1 * 32 + lid);
            float d0 = fabsf(a.x - b.x), d1 = fabsf(a.y - b.y);
            float d2 = fabsf(a.z - b.z), d3 = fabsf(a.w - b.w);
            uint32_t h01 = pack_bf16x2(d0, d1);
            uint32_t h23 = pack_bf16x2(d2, d3);
            uint32_t L01 = pack_bf16x2(d0 - __uint_as_float(h01 << 16),
                                       d1 - __uint_as_float(h01 & 0xffff0000u));
            uint32_t L23 = pack_bf16x2(d2 - __uint_as_float(h23 << 16),
                                       d3 - __uint_as_float(h23 & 0xffff0000u));
            uint32_t off = aw + (uint32_t)t * A_ROW_B + (uint32_t)lid * 8;
            sts64(off,             make_uint2(h01, h23));
            sts64(off + A_SPLIT_B, make_uint2(L01, L23));
        }
        __syncwarp();

        // ---- MMA: 2 m16-tiles x 8 n8-tiles x 8 k16-steps, 3-term split ----
        float acc[2][8][4];
        #pragma unroll
        for (int mt = 0; mt < 2; mt++)
            #pragma unroll
            for (int ns = 0; ns < 8; ns++)
                #pragma unroll
                for (int c = 0; c < 4; c++) acc[mt][ns][c] = 0.f;

        #pragma unroll 2
        for (int ks = 0; ks < 8; ks++) {
            uint32_t ahi0[4], ahi1[4], alo0[4], alo1[4];
            const uint32_t cb = (uint32_t)(ks * 32 + t4 * 4);
            ld_afrag(ahi0, aw,             0,  g2, cb);
            ld_afrag(ahi1, aw,             16, g2, cb);
            ld_afrag(alo0, aw + A_SPLIT_B, 0,  g2, cb);
            ld_afrag(alo1, aw + A_SPLIT_B, 16, g2, cb);
            const uint32_t bbase = (uint32_t)(ks * 2048 + lid * 8);
            #pragma unroll
            for (int ns = 0; ns < 8; ns++) {
                uint2 Bh = lds64(sb + SM_BHI + bbase + ns * 256);
                uint2 Bl = lds64(sb + SM_BLO + bbase + ns * 256);
                mma_bf16(acc[0][ns], ahi0, Bh);
                mma_bf16(acc[0][ns], ahi0, Bl);
                mma_bf16(acc[0][ns], alo0, Bh);
                mma_bf16(acc[1][ns], ahi1, Bh);
                mma_bf16(acc[1][ns], ahi1, Bl);
                mma_bf16(acc[1][ns], alo1, Bh);
            }
        }

        // ---- epilogue: h=relu(acc+b1); z=h.W2+b2; out=sigmoid(z) ----
        // D frag: c0=(g,2t) c1=(g,2t+1) c2=(g+8,2t) c3=(g+8,2t+1)
        #pragma unroll
        for (int mt = 0; mt < 2; mt++) {
            float za = par[128], zb = par[128];
            #pragma unroll
            for (int ns = 0; ns < 8; ns++) {
                int c0 = ns * 8 + 2 * t4, c1 = c0 + 1;
                float h;
                h = fmaxf(acc[mt][ns][0] + par[c0], 0.f); za = fmaf(h, par[64 + c0], za);
                h = fmaxf(acc[mt][ns][1] + par[c1], 0.f); za = fmaf(h, par[64 + c1], za);
                h = fmaxf(acc[mt][ns][2] + par[c0], 0.f); zb = fmaf(h, par[64 + c0], zb);
                h = fmaxf(acc[mt][ns][3] + par[c1], 0.f); zb = fmaf(h, par[64 + c1], zb);
            }
            za += __shfl_xor_sync(0xffffffffu, za, 1);
            za += __shfl_xor_sync(0xffffffffu, za, 2);
            zb += __shfl_xor_sync(0xffffffffu, zb, 1);
            zb += __shfl_xor_sync(0xffffffffu, zb, 2);
            if (t4 == 0) {
                int ea = e0 + mt * 16 + g2;
                int eb = ea + 8;
                if (ea < n_edges) out[ea] = 1.f / (1.f + __expf(-za));
                if (eb < n_edges) out[eb] = 1.f / (1.f + __expf(-zb));
            }
        }
        __syncwarp();
    }
}

extern "C" void kernel_launch(void* const* d_in, const int* in_sizes, int n_in,
                              void* d_out, int out_size) {
    const float* x   = (const float*)d_in[0];
    const int*   idx = (const int*)d_in[1];
    const float* W1  = (const float*)d_in[2];
    const float* b1  = (const float*)d_in[3];
    const float* W2  = (const float*)d_in[4];
    const float* b2  = (const float*)d_in[5];
    float*       out = (float*)d_out;

    int n_edges = in_sizes[1] / 2;                 // indices is [2, n_edges]
    int n_nodes = in_sizes[0] / D_FEAT;            // x is [n_nodes, 128] f32
    int n_tiles = (n_edges + TILE_E - 1) / TILE_E;

    int sms = 148;
    cudaDeviceGetAttribute(&sms, cudaDevAttrMultiProcessorCount, 0);

    detect_idx_kernel<<<1, 256>>>(idx, n_edges);

    cudaFuncSetAttribute(edge_mlp, cudaFuncAttributeMaxDynamicSharedMemorySize, SM_BYTES);
    edge_mlp<<<sms, THREADS, SM_BYTES>>>((const float4*)x, idx, W1, b1, W2, b2,
                                         out, n_edges, n_nodes, n_tiles, sms * WPC);
}

// round 5
// speedup vs baseline: 1.3006x; 1.3006x over previous
#include <cuda_runtime.h>
#include <cuda_bf16.h>
#include <cstdint>

// ============================================================================
// EdgeCompute: out[e] = sigmoid(relu(|x[i0[e]] - x[i1[e]]| @ W1 + b1) @ W2 + b2)
// Persistent kernel. 20 warps/CTA, 1 CTA/SM, warp-independent 16-edge tiles.
// Split-bf16 (hi+lo) mma.sync m16n8k16, 3-term product for fp32-grade accuracy.
// Index dtype (int32 vs int64) auto-detected by prepass.
// R5: occupancy 10->20 warps (TILE_E 32->16), B hi/lo merged into uint4 loads.
// ============================================================================

#define D_FEAT 128
#define HID 64
#define WPC 20
#define THREADS (WPC * 32)
#define TILE_E 16

#define A_ROW_B   272                   // 128 bf16 + 16B pad -> conflict-free frags
#define A_SPLIT_B (TILE_E * A_ROW_B)    // 4352
#define A_WARP_B  (2 * A_SPLIT_B)       // 8704
#define SM_A      0
#define SM_B      (WPC * A_WARP_B)      // 174080: 64 (ks,ns) x 32 lanes x uint4
#define SM_PAR    (SM_B + 64 * 512)     // 206848: b1[64], W2[64], b2
#define SM_BYTES  (SM_PAR + 132 * 4)    // 207376 < 232448

__device__ int g_idx_is64;   // 1 if indices are int64, 0 if int32

__device__ __forceinline__ uint32_t smem_u32(const void* p) {
    uint32_t a;
    asm("{ .reg .u64 t; cvta.to.shared.u64 t, %1; cvt.u32.u64 %0, t; }" : "=r"(a) : "l"(p));
    return a;
}
__device__ __forceinline__ uint32_t lds32(uint32_t addr) {
    uint32_t v;
    asm volatile("ld.shared.b32 %0, [%1];" : "=r"(v) : "r"(addr));
    return v;
}
__device__ __forceinline__ uint4 lds128(uint32_t addr) {
    uint4 v;
    asm volatile("ld.shared.v4.b32 {%0,%1,%2,%3}, [%4];"
                 : "=r"(v.x), "=r"(v.y), "=r"(v.z), "=r"(v.w) : "r"(addr));
    return v;
}
__device__ __forceinline__ void sts64(uint32_t addr, uint2 v) {
    asm volatile("st.shared.v2.b32 [%0], {%1,%2};" :: "r"(addr), "r"(v.x), "r"(v.y));
}
__device__ __forceinline__ void sts128(uint32_t addr, uint4 v) {
    asm volatile("st.shared.v4.b32 [%0], {%1,%2,%3,%4};"
                 :: "r"(addr), "r"(v.x), "r"(v.y), "r"(v.z), "r"(v.w));
}

// pack (lo16<-first arg, hi16<-second): cvt puts first PTX source in UPPER half.
__device__ __forceinline__ uint32_t pack_bf16x2(float lo, float hi) {
    uint32_t u;
    asm("cvt.rn.bf16x2.f32 %0, %1, %2;" : "=r"(u) : "f"(hi), "f"(lo));
    return u;
}

__device__ __forceinline__ void mma_bf16(float* c, const uint32_t* a,
                                         uint32_t b0, uint32_t b1) {
    asm volatile(
        "mma.sync.aligned.m16n8k16.row.col.f32.bf16.bf16.f32 "
        "{%0,%1,%2,%3}, {%4,%5,%6,%7}, {%8,%9}, {%0,%1,%2,%3};"
        : "+f"(c[0]), "+f"(c[1]), "+f"(c[2]), "+f"(c[3])
        : "r"(a[0]), "r"(a[1]), "r"(a[2]), "r"(a[3]), "r"(b0), "r"(b1));
}

// Load one m16k16 A fragment (4 u32): rows g, g+8; col words 2t.., 2t+8..
__device__ __forceinline__ void ld_afrag(uint32_t* f, uint32_t base, int g, uint32_t cb) {
    uint32_t r0 = base + (uint32_t)g * A_ROW_B + cb;
    uint32_t r8 = r0 + 8 * A_ROW_B;
    f[0] = lds32(r0);
    f[1] = lds32(r8);
    f[2] = lds32(r0 + 16);
    f[3] = lds32(r8 + 16);
}

// ---- prepass: int64 nonneg small values => every high word is 0 ----
__global__ void detect_idx_kernel(const int* __restrict__ idx32, int n_pairs) {
    __shared__ int s_or;
    if (threadIdx.x == 0) s_or = 0;
    __syncthreads();
    int v = 0;
    int lim = n_pairs < 4096 ? n_pairs : 4096;
    for (int j = threadIdx.x; j < lim; j += blockDim.x)
        v |= idx32[2 * j + 1];
    if (v) atomicOr(&s_or, 1);
    __syncthreads();
    if (threadIdx.x == 0) g_idx_is64 = (s_or == 0) ? 1 : 0;
}

__global__ void __launch_bounds__(THREADS, 1) edge_mlp(
    const float4* __restrict__ x4, const int* __restrict__ idx32,
    const float* __restrict__ W1, const float* __restrict__ b1,
    const float* __restrict__ W2, const float* __restrict__ b2,
    float* __restrict__ out, int n_edges, int n_nodes,
    int n_tiles, int n_warps_total)
{
    extern __shared__ char smem[];
    const uint32_t sb = smem_u32(smem);
    const int tid = threadIdx.x, wid = tid >> 5, lid = tid & 31;
    const int is64 = g_idx_is64;

    // ---- one-time: stage W1 as per-lane split-bf16 B fragments ----
    // (ks,ns) x lane: uint4 {Bh.x, Bh.y, Bl.x, Bl.y}. Lane L (g=L/4, t=L%4):
    //   Bh.x = {W1[16ks+2t][8ns+g], W1[16ks+2t+1][...]}, Bh.y = k rows +8,+9
    for (int e = tid; e < 2048; e += THREADS) {
        int tile = e >> 5, lane = e & 31;
        int ks = tile >> 3, ns = tile & 7;
        int g = lane >> 2, t = lane & 3;
        int col = ns * 8 + g;
        int kb = ks * 16 + 2 * t;
        float w00 = W1[(kb    ) * HID + col];
        float w01 = W1[(kb + 1) * HID + col];
        float w10 = W1[(kb + 8) * HID + col];
        float w11 = W1[(kb + 9) * HID + col];
        uint32_t h0 = pack_bf16x2(w00, w01);
        uint32_t h1 = pack_bf16x2(w10, w11);
        uint32_t l0 = pack_bf16x2(w00 - __uint_as_float(h0 << 16),
                                  w01 - __uint_as_float(h0 & 0xffff0000u));
        uint32_t l1 = pack_bf16x2(w10 - __uint_as_float(h1 << 16),
                                  w11 - __uint_as_float(h1 & 0xffff0000u));
        sts128(sb + SM_B + e * 16, make_uint4(h0, h1, l0, l1));
    }
    float* par = (float*)(smem + SM_PAR);
    if (tid < HID)            par[tid] = b1[tid];
    else if (tid < 2 * HID)   par[tid] = W2[tid - HID];
    if (tid == 2 * HID)       par[128] = b2[0];
    __syncthreads();

    const uint32_t aw = sb + SM_A + (uint32_t)wid * A_WARP_B;
    const int g2 = lid >> 2, t4 = lid & 3;

    // ---- persistent warp-independent tile loop ----
    for (int tile = blockIdx.x * WPC + wid; tile < n_tiles; tile += n_warps_total) {
        const int e0 = tile * TILE_E;
        // lanes 0..15 fetch this tile's indices (two per edge)
        int n0v = 0, n1v = 0;
        {
            int eg = e0 + (lid & 15);
            if (eg < n_edges) {
                if (is64) {
                    n0v = idx32[2 * eg];
                    n1v = idx32[2 * (n_edges + eg)];
                } else {
                    n0v = idx32[eg];
                    n1v = idx32[n_edges + eg];
                }
            }
            if ((unsigned)n0v >= (unsigned)n_nodes) n0v = 0;
            if ((unsigned)n1v >= (unsigned)n_nodes) n1v = 0;
        }
        __syncwarp();

        // gather + |diff| -> split-bf16 A rows (coalesced: full 512B row/edge)
        #pragma unroll 4
        for (int t = 0; t < TILE_E; t++) {
            int r0 = __shfl_sync(0xffffffffu, n0v, t);
            int r1 = __shfl_sync(0xffffffffu, n1v, t);
            float4 a = __ldg(x4 + r0 * 32 + lid);
            float4 b = __ldg(x4 + r1 * 32 + lid);
            float d0 = fabsf(a.x - b.x), d1 = fabsf(a.y - b.y);
            float d2 = fabsf(a.z - b.z), d3 = fabsf(a.w - b.w);
            uint32_t h01 = pack_bf16x2(d0, d1);
            uint32_t h23 = pack_bf16x2(d2, d3);
            uint32_t L01 = pack_bf16x2(d0 - __uint_as_float(h01 << 16),
                                       d1 - __uint_as_float(h01 & 0xffff0000u));
            uint32_t L23 = pack_bf16x2(d2 - __uint_as_float(h23 << 16),
                                       d3 - __uint_as_float(h23 & 0xffff0000u));
            uint32_t off = aw + (uint32_t)t * A_ROW_B + (uint32_t)lid * 8;
            sts64(off,             make_uint2(h01, h23));
            sts64(off + A_SPLIT_B, make_uint2(L01, L23));
        }
        __syncwarp();

        // ---- MMA: 1 m16-tile x 8 n8-tiles x 8 k16-steps, 3-term split ----
        float acc[8][4];
        #pragma unroll
        for (int ns = 0; ns < 8; ns++)
            #pragma unroll
            for (int c = 0; c < 4; c++) acc[ns][c] = 0.f;

        #pragma unroll 2
        for (int ks = 0; ks < 8; ks++) {
            uint32_t ahi[4], alo[4];
            const uint32_t cb = (uint32_t)(ks * 32 + t4 * 4);
            ld_afrag(ahi, aw,             g2, cb);
            ld_afrag(alo, aw + A_SPLIT_B, g2, cb);
            const uint32_t bbase = sb + SM_B + (uint32_t)(ks * 4096 + lid * 16);
            #pragma unroll
            for (int ns = 0; ns < 8; ns++) {
                uint4 B = lds128(bbase + ns * 512);
                mma_bf16(acc[ns], ahi, B.x, B.y);   // hi*hi
                mma_bf16(acc[ns], ahi, B.z, B.w);   // hi*lo
                mma_bf16(acc[ns], alo, B.x, B.y);   // lo*hi
            }
        }

        // ---- epilogue: h=relu(acc+b1); z=h.W2+b2; out=sigmoid(z) ----
        // D frag: c0=(g,2t) c1=(g,2t+1) c2=(g+8,2t) c3=(g+8,2t+1)
        float za = par[128], zb = par[128];
        #pragma unroll
        for (int ns = 0; ns < 8; ns++) {
            int c0 = ns * 8 + 2 * t4, c1 = c0 + 1;
            float h;
            h = fmaxf(acc[ns][0] + par[c0], 0.f); za = fmaf(h, par[64 + c0], za);
            h = fmaxf(acc[ns][1] + par[c1], 0.f); za = fmaf(h, par[64 + c1], za);
            h = fmaxf(acc[ns][2] + par[c0], 0.f); zb = fmaf(h, par[64 + c0], zb);
            h = fmaxf(acc[ns][3] + par[c1], 0.f); zb = fmaf(h, par[64 + c1], zb);
        }
        za += __shfl_xor_sync(0xffffffffu, za, 1);
        za += __shfl_xor_sync(0xffffffffu, za, 2);
        zb += __shfl_xor_sync(0xffffffffu, zb, 1);
        zb += __shfl_xor_sync(0xffffffffu, zb, 2);
        if (t4 == 0) {
            int ea = e0 + g2;
            int eb = ea + 8;
            if (ea < n_edges) out[ea] = 1.f / (1.f + __expf(-za));
            if (eb < n_edges) out[eb] = 1.f / (1.f + __expf(-zb));
        }
        __syncwarp();
    }
}

extern "C" void kernel_launch(void* const* d_in, const int* in_sizes, int n_in,
                              void* d_out, int out_size) {
    const float* x   = (const float*)d_in[0];
    const int*   idx = (const int*)d_in[1];
    const float* W1  = (const float*)d_in[2];
    const float* b1  = (const float*)d_in[3];
    const float* W2  = (const float*)d_in[4];
    const float* b2  = (const float*)d_in[5];
    float*       out = (float*)d_out;

    int n_edges = in_sizes[1] / 2;                 // indices is [2, n_edges]
    int n_nodes = in_sizes[0] / D_FEAT;            // x is [n_nodes, 128] f32
    int n_tiles = (n_edges + TILE_E - 1) / TILE_E;

    int sms = 148;
    cudaDeviceGetAttribute(&sms, cudaDevAttrMultiProcessorCount, 0);

    detect_idx_kernel<<<1, 256>>>(idx, n_edges);

    cudaFuncSetAttribute(edge_mlp, cudaFuncAttributeMaxDynamicSharedMemorySize, SM_BYTES);
    edge_mlp<<<sms, THREADS, SM_BYTES>>>((const float4*)x, idx, W1, b1, W2, b2,
                                         out, n_edges, n_nodes, n_tiles, sms * WPC);
}